// round 5
// baseline (speedup 1.0000x reference)
#include <cuda_runtime.h>

#define NC 4
#define CS 512
#define NS 256
#define HD 512
#define H  256
#define GAMMA_C 12.0f

// Tile config: CTA = 32 i-rows x 16 j-cols, 128 threads, each thread 2i x 2j
#define TI 32
#define TJ 16
#define TK 32          // k per stage
#define TKP 36         // padded row stride: 144B (16B-aligned rows), 4-bank shift -> conflict-free

// Scratch: rotated heads
__device__ float g_real[NC * CS * H];
__device__ float g_imag[NC * CS * H];

// ---------------- Kernel A: rotate heads by relation phase ----------------
__global__ void rotate_kernel(const float* __restrict__ heads,
                              const float* __restrict__ rel) {
    int i = blockIdx.x;      // 0..2047
    int k = threadIdx.x;     // 0..255
    float re = heads[i * HD + k];
    float im = heads[i * HD + H + k];
    float ph = rel[i * H + k] * 62.8318530717958648f;   // rel * (pi/0.05)
    float s, c;
    __sincosf(ph, &s, &c);
    g_real[i * H + k] = re * c - im * s;
    g_imag[i * H + k] = re * s + im * c;
}

// ---------------- f32x2 helpers ----------------
__device__ __forceinline__ unsigned long long addx2(unsigned long long a, unsigned long long b) {
    unsigned long long d;
    asm("add.rn.f32x2 %0, %1, %2;" : "=l"(d) : "l"(a), "l"(b));
    return d;
}
__device__ __forceinline__ unsigned long long mulx2(unsigned long long a, unsigned long long b) {
    unsigned long long d;
    asm("mul.rn.f32x2 %0, %1, %2;" : "=l"(d) : "l"(a), "l"(b));
    return d;
}
__device__ __forceinline__ unsigned long long fmax2(unsigned long long a, unsigned long long b, unsigned long long c) {
    unsigned long long d;
    asm("fma.rn.f32x2 %0, %1, %2, %3;" : "=l"(d) : "l"(a), "l"(b), "l"(c));
    return d;
}
__device__ __forceinline__ float sqrt_fast(float x) {
    float y;
    asm("sqrt.approx.f32 %0, %1;" : "=f"(y) : "f"(x));
    return y;
}
__device__ __forceinline__ unsigned long long lds64(const float* p) {
    return *reinterpret_cast<const unsigned long long*>(p);
}

// complex |h - t| for a packed pair of k; tails pre-negated so sub becomes add
__device__ __forceinline__ void accum_pair(unsigned long long rr, unsigned long long rm,
                                           unsigned long long tr, unsigned long long ti,
                                           float& a0, float& a1) {
    unsigned long long dr = addx2(rr, tr);
    unsigned long long di = addx2(rm, ti);
    unsigned long long s2 = mulx2(dr, dr);
    s2 = fmax2(di, di, s2);
    float lo, hi;
    asm("mov.b64 {%0, %1}, %2;" : "=f"(lo), "=f"(hi) : "l"(s2));
    a0 += sqrt_fast(lo);
    a1 += sqrt_fast(hi);
}

// ---------------- Kernel B: 128-thread tiled score, 2i x 2j per thread ----------------
__global__ __launch_bounds__(128, 10) void score_kernel(const float* __restrict__ tails,
                                                        float* __restrict__ out) {
    __shared__ __align__(16) float s_re[TI][TKP];
    __shared__ __align__(16) float s_im[TI][TKP];
    __shared__ __align__(16) float s_tr[TJ][TKP];   // negated tail real
    __shared__ __align__(16) float s_ti[TJ][TKP];   // negated tail imag

    const int tid = threadIdx.x;      // 0..127
    const int c   = blockIdx.z;
    const int bi  = blockIdx.x;       // 0..15
    const int bj  = blockIdx.y;       // 0..15

    const int tjx = tid & 7;          // j: tjx and tjx+8
    const int tix = tid >> 3;         // i: tix and tix+16

    const int gi0 = c * CS + bi * TI;
    const float* tbase = tails + (size_t)(c * NS + bj * TJ) * HD;

    float a00l = 0.f, a00h = 0.f;     // (i0, j0)
    float a01l = 0.f, a01h = 0.f;     // (i0, j1)
    float a10l = 0.f, a10h = 0.f;     // (i1, j0)
    float a11l = 0.f, a11h = 0.f;     // (i1, j1)

    for (int k0 = 0; k0 < H; k0 += TK) {
        __syncthreads();
        // stage heads: 32 rows x 32 floats = 256 float4 per array; 2 per thread
        #pragma unroll
        for (int s = 0; s < 2; s++) {
            int idx = tid + s * 128;          // 0..255
            int r   = idx >> 3;               // 0..31
            int c4  = (idx & 7) * 4;          // 0..28
            float4 v = *reinterpret_cast<const float4*>(&g_real[(size_t)(gi0 + r) * H + k0 + c4]);
            *reinterpret_cast<float4*>(&s_re[r][c4]) = v;
            float4 w = *reinterpret_cast<const float4*>(&g_imag[(size_t)(gi0 + r) * H + k0 + c4]);
            *reinterpret_cast<float4*>(&s_im[r][c4]) = w;
        }
        // stage tails (negated): 16 rows x 32 floats = 128 float4 per array; 1 per thread
        {
            int r  = tid >> 3;                // 0..15
            int c4 = (tid & 7) * 4;           // 0..28
            float4 v = *reinterpret_cast<const float4*>(&tbase[(size_t)r * HD + k0 + c4]);
            *reinterpret_cast<float4*>(&s_tr[r][c4]) = make_float4(-v.x, -v.y, -v.z, -v.w);
            float4 w = *reinterpret_cast<const float4*>(&tbase[(size_t)r * HD + H + k0 + c4]);
            *reinterpret_cast<float4*>(&s_ti[r][c4]) = make_float4(-w.x, -w.y, -w.z, -w.w);
        }
        __syncthreads();

        #pragma unroll
        for (int kk = 0; kk < TK; kk += 2) {
            unsigned long long tr0 = lds64(&s_tr[tjx][kk]);
            unsigned long long ti0 = lds64(&s_ti[tjx][kk]);
            unsigned long long tr1 = lds64(&s_tr[tjx + 8][kk]);
            unsigned long long ti1 = lds64(&s_ti[tjx + 8][kk]);
            unsigned long long rr0 = lds64(&s_re[tix][kk]);
            unsigned long long rm0 = lds64(&s_im[tix][kk]);
            unsigned long long rr1 = lds64(&s_re[tix + 16][kk]);
            unsigned long long rm1 = lds64(&s_im[tix + 16][kk]);

            accum_pair(rr0, rm0, tr0, ti0, a00l, a00h);
            accum_pair(rr0, rm0, tr1, ti1, a01l, a01h);
            accum_pair(rr1, rm1, tr0, ti0, a10l, a10h);
            accum_pair(rr1, rm1, tr1, ti1, a11l, a11h);
        }
    }

    const int gj = bj * TJ + tjx;
    const int gi = bi * TI + tix;
    out[((size_t)c * CS + gi)      * NS + gj]     = GAMMA_C - (a00l + a00h);
    out[((size_t)c * CS + gi)      * NS + gj + 8] = GAMMA_C - (a01l + a01h);
    out[((size_t)c * CS + gi + 16) * NS + gj]     = GAMMA_C - (a10l + a10h);
    out[((size_t)c * CS + gi + 16) * NS + gj + 8] = GAMMA_C - (a11l + a11h);
}

extern "C" void kernel_launch(void* const* d_in, const int* in_sizes, int n_in,
                              void* d_out, int out_size) {
    const float* heads = (const float*)d_in[0];
    const float* rel   = (const float*)d_in[1];
    const float* tails = (const float*)d_in[2];
    float* out = (float*)d_out;

    rotate_kernel<<<NC * CS, H>>>(heads, rel);
    dim3 grid(CS / TI, NS / TJ, NC);   // (16, 16, 4) = 1024 CTAs, single wave at 10 CTAs/SM
    score_kernel<<<grid, 128>>>(tails, out);
}

// round 6
// speedup vs baseline: 1.3420x; 1.3420x over previous
#include <cuda_runtime.h>

#define NC 4
#define CS 512
#define NS 256
#define HD 512
#define H  256
#define GAMMA_C 12.0f

// Tile config (R1-proven): CTA = 32 i x 16 j, 256 threads, 2i x 1j per thread
#define TI 32
#define TJ 16
#define TK 32
#define TKP 34         // 136B row stride: 8B-aligned (float2 ok), 2-bank shift -> conflict-free LDS.64

// Scratch: rotated heads
__device__ float g_real[NC * CS * H];
__device__ float g_imag[NC * CS * H];

// ---------------- Kernel A: rotate heads by relation phase ----------------
__global__ void rotate_kernel(const float* __restrict__ heads,
                              const float* __restrict__ rel) {
    int i = blockIdx.x;      // 0..2047
    int k = threadIdx.x;     // 0..255
    float re = heads[i * HD + k];
    float im = heads[i * HD + H + k];
    float ph = rel[i * H + k] * 62.8318530717958648f;   // rel * (pi/0.05)
    float s, c;
    __sincosf(ph, &s, &c);
    g_real[i * H + k] = re * c - im * s;
    g_imag[i * H + k] = re * s + im * c;
}

// ---------------- f32x2 helpers ----------------
__device__ __forceinline__ unsigned long long addx2(unsigned long long a, unsigned long long b) {
    unsigned long long d;
    asm("add.rn.f32x2 %0, %1, %2;" : "=l"(d) : "l"(a), "l"(b));
    return d;
}
__device__ __forceinline__ unsigned long long mulx2(unsigned long long a, unsigned long long b) {
    unsigned long long d;
    asm("mul.rn.f32x2 %0, %1, %2;" : "=l"(d) : "l"(a), "l"(b));
    return d;
}
__device__ __forceinline__ unsigned long long fmax2(unsigned long long a, unsigned long long b, unsigned long long c) {
    unsigned long long d;
    asm("fma.rn.f32x2 %0, %1, %2, %3;" : "=l"(d) : "l"(a), "l"(b), "l"(c));
    return d;
}
__device__ __forceinline__ float sqrt_fast(float x) {
    float y;
    asm("sqrt.approx.f32 %0, %1;" : "=f"(y) : "f"(x));
    return y;
}
__device__ __forceinline__ unsigned long long lds64(const float* p) {
    return *reinterpret_cast<const unsigned long long*>(p);
}

// ---------------- Kernel B: tiled score, single wave at 7 CTAs/SM ----------------
__global__ __launch_bounds__(256, 7) void score_kernel(const float* __restrict__ tails,
                                                       float* __restrict__ out) {
    __shared__ float s_re[TI][TKP];
    __shared__ float s_im[TI][TKP];
    __shared__ float s_tr[TJ][TKP];   // negated tail real
    __shared__ float s_ti[TJ][TKP];   // negated tail imag

    const int tid = threadIdx.x;
    const int c   = blockIdx.z;
    const int bi  = blockIdx.x;       // 0..15
    const int bj  = blockIdx.y;       // 0..15

    const int tjx = tid & 15;         // j within tile
    const int tix = tid >> 4;         // i within tile: rows tix and tix+16

    const int gi0 = c * CS + bi * TI;
    const float* tbase = tails + (size_t)(c * NS + bj * TJ) * HD;

    float accA0 = 0.f, accA1 = 0.f;
    float accB0 = 0.f, accB1 = 0.f;

    for (int k0 = 0; k0 < H; k0 += TK) {
        __syncthreads();
        // stage real/imag: 32 rows x 32 k = 512 float2 each; 2 per thread per array
        #pragma unroll
        for (int t = 0; t < 2; t++) {
            int idx = tid + t * 256;
            int r  = idx >> 4;
            int c2 = (idx & 15) * 2;
            float2 v = *reinterpret_cast<const float2*>(&g_real[(size_t)(gi0 + r) * H + k0 + c2]);
            *reinterpret_cast<float2*>(&s_re[r][c2]) = v;
            float2 w = *reinterpret_cast<const float2*>(&g_imag[(size_t)(gi0 + r) * H + k0 + c2]);
            *reinterpret_cast<float2*>(&s_im[r][c2]) = w;
        }
        // stage tails (negated): 16 rows x 32 k; 1 float2 per thread per array
        {
            int r  = tid >> 4;
            int c2 = (tid & 15) * 2;
            float2 v = *reinterpret_cast<const float2*>(&tbase[(size_t)r * HD + k0 + c2]);
            *reinterpret_cast<float2*>(&s_tr[r][c2]) = make_float2(-v.x, -v.y);
            float2 w = *reinterpret_cast<const float2*>(&tbase[(size_t)r * HD + H + k0 + c2]);
            *reinterpret_cast<float2*>(&s_ti[r][c2]) = make_float2(-w.x, -w.y);
        }
        __syncthreads();

        #pragma unroll
        for (int kk = 0; kk < TK; kk += 2) {
            unsigned long long tr2 = lds64(&s_tr[tjx][kk]);
            unsigned long long ti2 = lds64(&s_ti[tjx][kk]);
            {   // ii = 0
                unsigned long long rr = lds64(&s_re[tix][kk]);
                unsigned long long rm = lds64(&s_im[tix][kk]);
                unsigned long long dr = addx2(rr, tr2);
                unsigned long long di = addx2(rm, ti2);
                unsigned long long s2 = mulx2(dr, dr);
                s2 = fmax2(di, di, s2);
                float lo, hi;
                asm("mov.b64 {%0, %1}, %2;" : "=f"(lo), "=f"(hi) : "l"(s2));
                accA0 += sqrt_fast(lo);
                accA1 += sqrt_fast(hi);
            }
            {   // ii = 1
                unsigned long long rr = lds64(&s_re[tix + 16][kk]);
                unsigned long long rm = lds64(&s_im[tix + 16][kk]);
                unsigned long long dr = addx2(rr, tr2);
                unsigned long long di = addx2(rm, ti2);
                unsigned long long s2 = mulx2(dr, dr);
                s2 = fmax2(di, di, s2);
                float lo, hi;
                asm("mov.b64 {%0, %1}, %2;" : "=f"(lo), "=f"(hi) : "l"(s2));
                accB0 += sqrt_fast(lo);
                accB1 += sqrt_fast(hi);
            }
        }
    }

    const int gj = bj * TJ + tjx;
    const int gi = bi * TI + tix;
    out[((size_t)c * CS + gi)      * NS + gj] = GAMMA_C - (accA0 + accA1);
    out[((size_t)c * CS + gi + 16) * NS + gj] = GAMMA_C - (accB0 + accB1);
}

extern "C" void kernel_launch(void* const* d_in, const int* in_sizes, int n_in,
                              void* d_out, int out_size) {
    const float* heads = (const float*)d_in[0];
    const float* rel   = (const float*)d_in[1];
    const float* tails = (const float*)d_in[2];
    float* out = (float*)d_out;

    rotate_kernel<<<NC * CS, H>>>(heads, rel);
    dim3 grid(CS / TI, NS / TJ, NC);   // (16, 16, 4) = 1024 CTAs, single wave at 7 CTAs/SM
    score_kernel<<<grid, 256>>>(tails, out);
}